// round 2
// baseline (speedup 1.0000x reference)
#include <cuda_runtime.h>

#define BATCH      1024
#define INPUT_DIM  1024
#define NB_K       32
#define KDIM       16
#define OUT_COLS   (INPUT_DIM + NB_K)   // 1056

// Scratch for activations, laid out [k][b][m] so each k-slice is contiguous.
__device__ float g_act[(size_t)NB_K * BATCH * KDIM];   // 2 MB

// ---------------------------------------------------------------------------
// Kernel A: act[k][b][m] = sum_d x[b][d] * W[k][d][m]
// grid = (32 k, 4 b-tiles), block = 256 threads (one b-row per thread).
// ---------------------------------------------------------------------------
__global__ void __launch_bounds__(256) mbd_gemm_kernel(
    const float* __restrict__ x, const float* __restrict__ W)
{
    const int k   = blockIdx.x;
    const int b0  = blockIdx.y * 256;
    const int tid = threadIdx.x;

    __shared__ float sx[256][33];   // padded: bank-conflict-free column reads
    __shared__ float sw[32][16];

    float acc[16];
#pragma unroll
    for (int m = 0; m < 16; m++) acc[m] = 0.f;

    const float4* x4 = reinterpret_cast<const float4*>(x);

    for (int d0 = 0; d0 < INPUT_DIM; d0 += 32) {
        // --- load x tile: 256 rows x 32 cols = 2048 float4, 8 per thread ---
#pragma unroll
        for (int i = 0; i < 8; i++) {
            int idx = tid + i * 256;
            int r = idx >> 3;
            int c = idx & 7;
            float4 v = x4[(size_t)(b0 + r) * (INPUT_DIM / 4) + (d0 >> 2) + c];
            sx[r][c * 4 + 0] = v.x;
            sx[r][c * 4 + 1] = v.y;
            sx[r][c * 4 + 2] = v.z;
            sx[r][c * 4 + 3] = v.w;
        }
        // --- load W tile: W[k][d0..d0+31][0..15] is 512 contiguous floats ---
        if (tid < 128) {
            const float4* w4 = reinterpret_cast<const float4*>(
                W + (size_t)k * INPUT_DIM * KDIM + (size_t)d0 * KDIM);
            reinterpret_cast<float4*>(&sw[0][0])[tid] = w4[tid];
        }
        __syncthreads();

#pragma unroll
        for (int dd = 0; dd < 32; dd++) {
            float xv = sx[tid][dd];
            const float4* wr = reinterpret_cast<const float4*>(&sw[dd][0]);
            float4 w0 = wr[0], w1 = wr[1], w2 = wr[2], w3 = wr[3];
            acc[0]  += xv * w0.x;  acc[1]  += xv * w0.y;
            acc[2]  += xv * w0.z;  acc[3]  += xv * w0.w;
            acc[4]  += xv * w1.x;  acc[5]  += xv * w1.y;
            acc[6]  += xv * w1.z;  acc[7]  += xv * w1.w;
            acc[8]  += xv * w2.x;  acc[9]  += xv * w2.y;
            acc[10] += xv * w2.z;  acc[11] += xv * w2.w;
            acc[12] += xv * w3.x;  acc[13] += xv * w3.y;
            acc[14] += xv * w3.z;  acc[15] += xv * w3.w;
        }
        __syncthreads();
    }

    float4* o4 = reinterpret_cast<float4*>(
        g_act + ((size_t)k * BATCH + b0 + tid) * KDIM);
    o4[0] = make_float4(acc[0],  acc[1],  acc[2],  acc[3]);
    o4[1] = make_float4(acc[4],  acc[5],  acc[6],  acc[7]);
    o4[2] = make_float4(acc[8],  acc[9],  acc[10], acc[11]);
    o4[3] = make_float4(acc[12], acc[13], acc[14], acc[15]);
}

// ---------------------------------------------------------------------------
// Kernel B: feat[b][k] = sum_c exp(-sum_m |act[k][b][m] - act[k][c][m]|)
// grid = (32 k, 4 b-tiles), block = 256 (one b per thread).
// act_k staged through shared in two 512-row chunks (32 KB static smem).
// ---------------------------------------------------------------------------
__global__ void __launch_bounds__(256) mbd_pairwise_kernel(float* __restrict__ out)
{
    const int k   = blockIdx.x;
    const int tid = threadIdx.x;
    const int b   = blockIdx.y * 256 + tid;

    __shared__ float4 sa[512 * 4];   // 512 rows x 16 floats = 32 KB

    const float4* actk = reinterpret_cast<const float4*>(
        g_act + (size_t)k * BATCH * KDIM);

    // my own activation row (16 floats)
    float4 a0 = actk[b * 4 + 0];
    float4 a1 = actk[b * 4 + 1];
    float4 a2 = actk[b * 4 + 2];
    float4 a3 = actk[b * 4 + 3];

    float f = 0.f;

    for (int c0 = 0; c0 < BATCH; c0 += 512) {
        __syncthreads();   // previous chunk fully consumed before overwrite
#pragma unroll
        for (int i = 0; i < 8; i++)
            sa[tid + i * 256] = actk[c0 * 4 + tid + i * 256];
        __syncthreads();

#pragma unroll 4
        for (int c = 0; c < 512; c++) {
            float4 v0 = sa[c * 4 + 0];
            float4 v1 = sa[c * 4 + 1];
            float4 v2 = sa[c * 4 + 2];
            float4 v3 = sa[c * 4 + 3];
            float s0 = fabsf(a0.x - v0.x) + fabsf(a0.y - v0.y)
                     + fabsf(a0.z - v0.z) + fabsf(a0.w - v0.w);
            float s1 = fabsf(a1.x - v1.x) + fabsf(a1.y - v1.y)
                     + fabsf(a1.z - v1.z) + fabsf(a1.w - v1.w);
            float s2 = fabsf(a2.x - v2.x) + fabsf(a2.y - v2.y)
                     + fabsf(a2.z - v2.z) + fabsf(a2.w - v2.w);
            float s3 = fabsf(a3.x - v3.x) + fabsf(a3.y - v3.y)
                     + fabsf(a3.z - v3.z) + fabsf(a3.w - v3.w);
            float s = (s0 + s1) + (s2 + s3);
            f += __expf(-s);
        }
    }

    out[(size_t)b * OUT_COLS + INPUT_DIM + k] = f;
}

// ---------------------------------------------------------------------------
// Kernel C: copy x into out[:, 0:1024] (float4, both strides 16B-aligned)
// ---------------------------------------------------------------------------
__global__ void __launch_bounds__(256) mbd_copy_kernel(
    const float* __restrict__ x, float* __restrict__ out)
{
    const float4* x4 = reinterpret_cast<const float4*>(x);
    float4*       o4 = reinterpret_cast<float4*>(out);
    int idx0 = blockIdx.x * 256 + threadIdx.x;
    const int stride = gridDim.x * 256;
    const int n4 = BATCH * (INPUT_DIM / 4);          // 262144
#pragma unroll 4
    for (int idx = idx0; idx < n4; idx += stride) {
        int bRow = idx >> 8;          // / 256 float4 per x row
        int j    = idx & 255;
        o4[(size_t)bRow * (OUT_COLS / 4) + j] = x4[idx];
    }
}

extern "C" void kernel_launch(void* const* d_in, const int* in_sizes, int n_in,
                              void* d_out, int out_size)
{
    (void)in_sizes; (void)n_in; (void)out_size;
    const float* x = (const float*)d_in[0];
    const float* W = (const float*)d_in[1];
    float* out = (float*)d_out;

    mbd_gemm_kernel<<<dim3(NB_K, BATCH / 256), 256>>>(x, W);
    mbd_pairwise_kernel<<<dim3(NB_K, BATCH / 256), 256>>>(out);
    mbd_copy_kernel<<<256, 256>>>(x, out);
}